// round 8
// baseline (speedup 1.0000x reference)
#include <cuda_runtime.h>

// Round 8: 128-bit everything.
//  - feat pitch 129 -> 132 (conflict-free LDS.128), conv inner loop float4:
//    1 LDS.128 + 4 uniform LDG.128 + 16 FFMA per 4 ic.
//  - pool/conv1x1 reads a1 rows as 4x LDS.128 broadcast (was 16 scalar LDS).
//  - a1 assembly + bias init vectorized float4.
//  - mappings / determinism identical to round 7.
namespace {

constexpr int GRID_H = 13;
constexpr int GRID_W = 3;
constexpr int G      = GRID_H * GRID_W;   // 39
constexpr int ENC    = 128;
constexpr int TS     = 16;
constexpr int C31    = 16;
constexpr int C11    = 32;
constexpr int SOCD   = 64;
constexpr int KN     = 32;
constexpr int U      = 4;                 // batches per block
constexpr int FPITCH = 132;               // /4 for float4; (33*l)%8 distinct -> LDS128 ok
constexpr int MAXJ   = U * KN;
constexpr int FCD    = 160;

__device__ __align__(16) float wT[3 * ENC * C31];     // [kh][ic][oc16]
__device__ __align__(16) float fcwT[FCD * SOCD];      // [f][o]

__device__ __forceinline__ float lrelu(float x) { return x > 0.0f ? x : 0.1f * x; }

__global__ void prep_kernel(const float* __restrict__ w31,
                            const float* __restrict__ fcw)
{
    int i = blockIdx.x * 256 + threadIdx.x;
    if (i < 3 * ENC * C31) {
        int kh = i >> 11;
        int r  = i & 2047;
        int ic = r >> 4, oc = r & 15;
        wT[i] = w31[(oc * ENC + ic) * 3 + kh];
    }
    if (i < FCD * SOCD) {
        int f = i >> 6, o = i & 63;
        fcwT[i] = fcw[o * FCD + f];
    }
}

__global__ __launch_bounds__(256, 6)
void csp_kernel(const float* __restrict__ enc,   // [N_VEH,128,16]
                const int*   __restrict__ nb,    // [B,32]
                const int*   __restrict__ gp,    // [N_VEH,2]
                const float* __restrict__ b31,   // [16]
                const float* __restrict__ w11,   // [32,16]
                const float* __restrict__ b11,   // [32]
                const float* __restrict__ fcb,   // [64]
                float*       __restrict__ out,   // [B,64]
                int batch)
{
    __shared__ __align__(16) float featC[32 * FPITCH];   // 16896B; later red[4][64][4]
    __shared__ __align__(16) float yT[32 * 3 * C31];     // 6144B; later p[160][4]
    __shared__ __align__(16) float a1[U * G * C31];      // 9984B; winner ints at start
    __shared__ __align__(16) float w11s[C31 * C11];      // [ic][oc]
    __shared__ __align__(16) float b31s[C31];
    __shared__ float b11s[C11];
    __shared__ int   jOf[U * G];
    __shared__ int   vehG[MAXJ];
    __shared__ int   totCnt;

    const int b0  = blockIdx.x * U;
    const int tid = threadIdx.x;
    const int wid = tid >> 5;
    const int lan = tid & 31;

    // ---- stage small weights / init ----
    for (int i = tid; i < C31 * C11; i += 256) {
        int ic = i >> 5, oc = i & 31;
        w11s[i] = __ldg(w11 + oc * C31 + ic);
    }
    if (tid < C31) b31s[tid] = __ldg(b31 + tid);
    if (tid < C11) b11s[tid] = __ldg(b11 + tid);
    if (tid < U * G) jOf[tid] = -1;
    if (tid == 0) totCnt = 0;
    int* winner = (int*)a1;
    if (tid < U * G) winner[tid] = -1;
    __syncthreads();

    // ---- winners per cell ----
    if (tid < U * KN) {
        int u = tid >> 5, k = tid & 31;
        int b = b0 + u;
        if (b < batch) {
            int v = nb[b * KN + k];
            int x = __ldg(gp + 2 * v), yy = __ldg(gp + 2 * v + 1);
            if (x >= 0 && x < GRID_H && yy >= 0 && yy < GRID_W)
                atomicMax(&winner[u * G + x * GRID_W + yy], k);
        }
    }
    __syncthreads();
    if (tid < U * G) {
        int w = winner[tid];
        if (w >= 0) {
            int u = tid / G;
            int v = nb[(b0 + u) * KN + w];
            int j = atomicAdd(&totCnt, 1);
            jOf[tid] = j;
            vehG[j]  = v;
        }
    }
    __syncthreads();
    const int tot    = totCnt;
    const int ntiles = (tot + 31) >> 5;

    // ---- init a1 = bias (float4; winner scratch dead) ----
    {
        const float4* bv = (const float4*)b31s;
        float4* a1v = (float4*)a1;
        for (int e = tid; e < U * G * 4; e += 256)
            a1v[e] = bv[e & 3];
    }
    __syncthreads();

    // ---- tiles: gather -> conv3x1 partials -> accumulate a1 ----
    for (int t = 0; t < ntiles; ++t) {
        const int  jBase = t << 5;
        const int  nT    = min(32, tot - jBase);
        const bool last  = (t == ntiles - 1);

        for (int i = tid; i < (nT << 7); i += 256) {
            int s = i >> 7, ic = i & 127;
            int v = vehG[jBase + s];
            featC[s * FPITCH + ic] =
                __ldg(enc + (size_t)v * (ENC * TS) + ic * TS + (TS - 1));
        }
        __syncthreads();

        // conv: warp-task c=(kh,ocg); lane=slot. float4 feat + uniform float4 weights.
        for (int c = wid; c < 12; c += 8) {
            int kh = c >> 2, ocg = c & 3;
            const float4* wr  = (const float4*)wT + (kh << 9) + ocg;
            const float4* frv = (const float4*)(featC + lan * FPITCH);
            float4 acc = make_float4(0.f, 0.f, 0.f, 0.f);
            #pragma unroll 8
            for (int i4 = 0; i4 < 32; ++i4) {
                float4 f  = frv[i4];
                float4 w0 = __ldg(wr + ((i4 << 2) + 0) * 4);
                float4 w1 = __ldg(wr + ((i4 << 2) + 1) * 4);
                float4 w2 = __ldg(wr + ((i4 << 2) + 2) * 4);
                float4 w3 = __ldg(wr + ((i4 << 2) + 3) * 4);
                acc.x += f.x * w0.x + f.y * w1.x + f.z * w2.x + f.w * w3.x;
                acc.y += f.x * w0.y + f.y * w1.y + f.z * w2.y + f.w * w3.y;
                acc.z += f.x * w0.z + f.y * w1.z + f.z * w2.z + f.w * w3.z;
                acc.w += f.x * w0.w + f.y * w1.w + f.z * w2.w + f.w * w3.w;
            }
            if (lan < nT)
                *(float4*)(yT + lan * 48 + (kh << 4) + (ocg << 2)) = acc;
        }
        __syncthreads();

        // accumulate tile partials into a1 (float4; fixed ownership -> deterministic)
        for (int e = tid; e < U * G * 4; e += 256) {
            int u   = e / (G * 4);
            int r   = e - u * (G * 4);
            int pos = r >> 2, g = r & 3;
            int h = pos / 3, w = pos - h * 3;
            float4 val = ((float4*)a1)[e];
            #pragma unroll
            for (int dh = -1; dh <= 1; ++dh) {
                int hh = h + dh;
                if ((unsigned)hh < (unsigned)GRID_H) {
                    int j = jOf[u * G + hh * 3 + w];
                    int s = j - jBase;
                    if (s >= 0 && s < nT) {
                        float4 yv = *(const float4*)(yT + s * 48 + ((dh + 1) << 4) + (g << 2));
                        val.x += yv.x; val.y += yv.y; val.z += yv.z; val.w += yv.w;
                    }
                }
            }
            if (last) {
                val.x = lrelu(val.x); val.y = lrelu(val.y);
                val.z = lrelu(val.z); val.w = lrelu(val.w);
            }
            ((float4*)a1)[e] = val;
        }
        __syncthreads();
    }
    if (ntiles == 0) {
        for (int e = tid; e < U * G * 4; e += 256) {
            float4 v = ((float4*)a1)[e];
            v.x = lrelu(v.x); v.y = lrelu(v.y); v.z = lrelu(v.z); v.w = lrelu(v.w);
            ((float4*)a1)[e] = v;
        }
        __syncthreads();
    }

    // ---- conv1x1 + lrelu + 3x3/3 maxpool. warp-task=(u,ph), lane=oc2.
    //      a1 rows read as 4x LDS.128 broadcast. ----
    float* const p = yT;   // p[f][u], f = oc2*5+ph; yT dead
    for (int wt = wid; wt < U * 5; wt += 8) {
        int u = wt / 5, ph = wt - u * 5;
        float wr[16];
        #pragma unroll
        for (int ic = 0; ic < 16; ++ic) wr[ic] = w11s[(ic << 5) + lan];
        float bias = b11s[lan];
        float m = -3.4e38f;
        int h1 = min(3 * ph + 3, GRID_H);
        for (int h = 3 * ph; h < h1; ++h) {
            #pragma unroll
            for (int w = 0; w < 3; ++w) {
                const float4* ar = (const float4*)(a1 + u * (G * C31) + ((h * 3 + w) << 4));
                float4 q0 = ar[0], q1 = ar[1], q2 = ar[2], q3 = ar[3];
                float s = bias
                    + q0.x * wr[0]  + q0.y * wr[1]  + q0.z * wr[2]  + q0.w * wr[3]
                    + q1.x * wr[4]  + q1.y * wr[5]  + q1.z * wr[6]  + q1.w * wr[7]
                    + q2.x * wr[8]  + q2.y * wr[9]  + q2.z * wr[10] + q2.w * wr[11]
                    + q3.x * wr[12] + q3.y * wr[13] + q3.z * wr[14] + q3.w * wr[15];
                m = fmaxf(m, lrelu(s));
            }
        }
        p[((lan * 5 + ph) << 2) + u] = m;
    }
    __syncthreads();

    // ---- FC 160->64 cooperative: warp=(o-half, f-quarter) ----
    float* const red = featC;                    // red[fq][o][u]; featC dead
    {
        int orr = wid & 1, fq = wid >> 1;
        int o = (orr << 5) + lan;
        float a0 = 0.f, s1 = 0.f, a2 = 0.f, a3 = 0.f;
        int f0 = fq * 40;
        #pragma unroll 8
        for (int f = f0; f < f0 + 40; ++f) {
            float  wv = __ldg(fcwT + (f << 6) + o);        // 1 line / warp
            float4 pv = *(const float4*)(p + (f << 2));    // uniform
            a0 += wv * pv.x; s1 += wv * pv.y;
            a2 += wv * pv.z; a3 += wv * pv.w;
        }
        *(float4*)(red + ((fq << 6) + o) * 4) = make_float4(a0, s1, a2, a3);
    }
    __syncthreads();
    {
        int u = tid >> 6, o = tid & 63;
        int b = b0 + u;
        if (b < batch) {
            float acc = __ldg(fcb + o);
            #pragma unroll
            for (int fq = 0; fq < 4; ++fq)
                acc += red[((fq << 6) + o) * 4 + u];
            out[b * SOCD + o] = lrelu(acc);
        }
    }
}

} // namespace

extern "C" void kernel_launch(void* const* d_in, const int* in_sizes, int n_in,
                              void* d_out, int out_size)
{
    const float* enc = (const float*)d_in[0];
    const int*   nb  = (const int*)  d_in[1];
    const int*   gp  = (const int*)  d_in[2];
    const float* w31 = (const float*)d_in[3];
    const float* b31 = (const float*)d_in[4];
    const float* w11 = (const float*)d_in[5];
    const float* b11 = (const float*)d_in[6];
    const float* fcw = (const float*)d_in[7];
    const float* fcb = (const float*)d_in[8];
    float* out = (float*)d_out;

    const int batch = in_sizes[1] / KN;   // 8192

    prep_kernel<<<(FCD * SOCD + 255) / 256, 256>>>(w31, fcw);
    csp_kernel<<<(batch + U - 1) / U, 256>>>(enc, nb, gp, b31, w11, b11, fcb, out, batch);
}